// round 10
// baseline (speedup 1.0000x reference)
#include <cuda_runtime.h>
#include <cstdint>

// ============================================================================
// Problem constants
// ============================================================================
#define GAMMA_F 0.00390625f

constexpr int B_ROWS = 65536;
constexpr int FEAT   = 256;
constexpr int S_DIM  = 1024;

constexpr int BM  = 64;
constexpr int BN  = 128;
constexpr int NTH = 256;

constexpr float INV254 = 1.0f / 254.0f;
constexpr float INVQ   = 1.0f / 16129.0f;   // 1/127^2
constexpr float H_SCALE = 1.25f;            // fixed quant scale for hidden h

// SMEM stage bytes for a given BK (rows padded +16B)
constexpr int stage_bytes(int bk) { return 2 * BM * (bk + 16) + 2 * BN * (bk + 16); }
constexpr int SMEM_G1 = 2 * stage_bytes(64);    // 61440
constexpr int SMEM_G2 = 2 * stage_bytes(128);   // 110592

// ============================================================================
// Device scratch (__device__ globals: alloc-free rule)
// ============================================================================
__device__ __align__(16) int8_t g_xa [(size_t)B_ROWS * FEAT];
__device__ __align__(16) int8_t g_xb [(size_t)B_ROWS * FEAT];
__device__ __align__(16) int8_t g_sva[(size_t)S_DIM * FEAT];
__device__ __align__(16) int8_t g_svb[(size_t)S_DIM * FEAT];
__device__ __align__(16) int8_t g_w1a[(size_t)S_DIM * S_DIM];
__device__ __align__(16) int8_t g_w1b[(size_t)S_DIM * S_DIM];
__device__ __align__(16) int8_t g_w2a[(size_t)S_DIM * S_DIM];
__device__ __align__(16) int8_t g_w2b[(size_t)S_DIM * S_DIM];
__device__ __align__(16) int8_t g_ka [(size_t)B_ROWS * S_DIM];
__device__ __align__(16) int8_t g_kb [(size_t)B_ROWS * S_DIM];
__device__ __align__(16) int8_t g_ha [(size_t)B_ROWS * S_DIM];
__device__ __align__(16) int8_t g_hb [(size_t)B_ROWS * S_DIM];
__device__ float g_xs [B_ROWS];
__device__ float g_svs[S_DIM];
__device__ float g_w1s[S_DIM];
__device__ float g_w2s[S_DIM];
__device__ float g_xn [B_ROWS];
__device__ float g_svn[S_DIM];
__device__ float g_part[32 * B_ROWS * 2];

// ============================================================================
// PTX helpers
// ============================================================================
__device__ __forceinline__ uint32_t smem_u32(const void* p) {
    uint32_t a;
    asm("{ .reg .u64 t; cvta.to.shared.u64 t, %1; cvt.u32.u64 %0, t; }"
        : "=r"(a) : "l"(p));
    return a;
}

__device__ __forceinline__ void cp16(uint32_t s, const void* g) {
    asm volatile("cp.async.cg.shared.global [%0], [%1], 16;"
                 :: "r"(s), "l"((unsigned long long)(uintptr_t)g) : "memory");
}
#define CP_COMMIT()  asm volatile("cp.async.commit_group;" ::: "memory")
#define CP_WAIT0()   asm volatile("cp.async.wait_group 0;" ::: "memory")

__device__ __forceinline__ void ldm_x4(uint32_t* r, uint32_t saddr) {
    asm volatile("ldmatrix.sync.aligned.m8n8.x4.shared.b16 {%0,%1,%2,%3}, [%4];"
                 : "=r"(r[0]), "=r"(r[1]), "=r"(r[2]), "=r"(r[3]) : "r"(saddr));
}

#define IMMA(C, A, B0, B1)                                                     \
    asm volatile(                                                              \
        "mma.sync.aligned.m16n8k32.row.col.s32.s8.s8.s32 "                     \
        "{%0,%1,%2,%3}, {%4,%5,%6,%7}, {%8,%9}, {%0,%1,%2,%3};"                \
        : "+r"((C)[0]), "+r"((C)[1]), "+r"((C)[2]), "+r"((C)[3])               \
        : "r"((A)[0]), "r"((A)[1]), "r"((A)[2]), "r"((A)[3]),                  \
          "r"(B0), "r"(B1))

// fp32 -> 2-slice int8 (inv = 127/scale), clamped
__device__ __forceinline__ void qpair(float v, float inv, int8_t& o1, int8_t& o2) {
    float q = fminf(fmaxf(v * inv, -127.0f), 127.0f);
    float R = rintf(q);
    o1 = (int8_t)(int)R;
    o2 = (int8_t)(int)rintf((q - R) * 254.0f);
}

// ============================================================================
// Row-wise 2-slice quantizer (warp per row)
// ============================================================================
template <int COLS, bool NORM>
__global__ void quant_rows(const float* __restrict__ src,
                           int8_t* __restrict__ q1, int8_t* __restrict__ q2,
                           float* __restrict__ sOut, float* __restrict__ nrm) {
    int row  = blockIdx.x * 8 + (threadIdx.x >> 5);
    int lane = threadIdx.x & 31;
    const float4* s4 = (const float4*)(src + (size_t)row * COLS);
    float4 vb[COLS / 128];
    float mx = 0.f, ss = 0.f;
    #pragma unroll
    for (int i = 0; i < COLS / 128; ++i) {
        float4 v = s4[i * 32 + lane];
        vb[i] = v;
        mx = fmaxf(mx, fmaxf(fmaxf(fabsf(v.x), fabsf(v.y)),
                             fmaxf(fabsf(v.z), fabsf(v.w))));
        if (NORM)
            ss = fmaf(v.x, v.x, fmaf(v.y, v.y, fmaf(v.z, v.z, fmaf(v.w, v.w, ss))));
    }
    #pragma unroll
    for (int o = 16; o; o >>= 1) {
        mx = fmaxf(mx, __shfl_xor_sync(0xffffffffu, mx, o));
        if (NORM) ss += __shfl_xor_sync(0xffffffffu, ss, o);
    }
    float s = mx > 0.f ? mx : 1.0f;
    if (lane == 0) {
        sOut[row] = s;
        if (NORM) nrm[row] = ss;
    }
    float inv = 127.0f / s;
    #pragma unroll
    for (int i = 0; i < COLS / 128; ++i) {
        char4 c1, c2;
        qpair(vb[i].x, inv, (int8_t&)c1.x, (int8_t&)c2.x);
        qpair(vb[i].y, inv, (int8_t&)c1.y, (int8_t&)c2.y);
        qpair(vb[i].z, inv, (int8_t&)c1.z, (int8_t&)c2.z);
        qpair(vb[i].w, inv, (int8_t&)c1.w, (int8_t&)c2.w);
        size_t o = (size_t)row * COLS + i * 128 + lane * 4;
        *(char4*)(q1 + o) = c1;
        *(char4*)(q2 + o) = c2;
    }
}

// ============================================================================
// Int8 2-slice GEMM (templated BK).  D[m,n] = sum_k A[m,k] * B[n,k]
//  dot = (C1 + Cx/254) * sA*sB/127^2,  C1 = A1B1, Cx = A1B2 + A2B1
//  EPI 0: k = exp(g*(2*dot - xn - svn)) -> g_ka/g_kb (scale 1)
//  EPI 1: h = relu(dot + b1)            -> g_ha/g_hb (fixed scale H_SCALE)
//  EPI 2: v = relu(dot + b2); head partials -> g_part
// ============================================================================
template <int KTOT, int BKT, int EPI>
__global__ void __launch_bounds__(NTH, 2)
gemm_i8(const int8_t* __restrict__ A1p, const int8_t* __restrict__ A2p,
        const int8_t* __restrict__ B1p, const int8_t* __restrict__ B2p,
        const float* __restrict__ sA, float sAc, const float* __restrict__ sB,
        const float* __restrict__ bias, const float* __restrict__ Wh) {
    constexpr int ROWB    = BKT + 16;
    constexpr int A_PLANE = BM * ROWB;
    constexpr int B_PLANE = BN * ROWB;
    constexpr int OFF_A1  = 0;
    constexpr int OFF_A2  = A_PLANE;
    constexpr int OFF_B1  = 2 * A_PLANE;
    constexpr int OFF_B2  = 2 * A_PLANE + B_PLANE;
    constexpr int STAGE   = 2 * A_PLANE + 2 * B_PLANE;
    constexpr int NKK     = BKT / 32;

    extern __shared__ char smem[];
    const uint32_t sb0 = smem_u32(smem);

    const int tid    = threadIdx.x;
    const int wid    = tid >> 5;
    const int lane   = tid & 31;
    const int g      = lane >> 2;
    const int tg     = lane & 3;
    const int warp_m = wid & 1;         // 0..1  (32-row halves)
    const int warp_n = wid >> 1;        // 0..3  (32-col slices)

    const int rowBase = blockIdx.y * BM;
    const int colBase = blockIdx.x * BN;
    constexpr int NCHUNK = KTOT / BKT;

    const int a_row = warp_m * 32 + (lane & 7) + ((lane >> 3) & 1) * 8;
    const int a_kby = (lane >> 4) * 16;
    const int b_row = warp_n * 32 + (lane & 7) + (lane >> 4) * 8;
    const int b_kby = ((lane >> 3) & 1) * 16;

    auto load_stage = [&](int c) {
        uint32_t s0 = sb0 + (c & 1) * STAGE;
        const int kc = c * BKT;
        constexpr int SEG = BKT / 16;
        #pragma unroll
        for (int u = tid; u < BM * SEG; u += NTH) {
            int row = u / SEG, seg = u % SEG;
            size_t go = (size_t)(rowBase + row) * KTOT + kc + seg * 16;
            cp16(s0 + OFF_A1 + row * ROWB + seg * 16, A1p + go);
            cp16(s0 + OFF_A2 + row * ROWB + seg * 16, A2p + go);
        }
        #pragma unroll
        for (int u = tid; u < BN * SEG; u += NTH) {
            int row = u / SEG, seg = u % SEG;
            size_t go = (size_t)(colBase + row) * KTOT + kc + seg * 16;
            cp16(s0 + OFF_B1 + row * ROWB + seg * 16, B1p + go);
            cp16(s0 + OFF_B2 + row * ROWB + seg * 16, B2p + go);
        }
        CP_COMMIT();
    };

    int C1[2][4][4], Cx[2][4][4];
    #pragma unroll
    for (int mt = 0; mt < 2; ++mt)
        #pragma unroll
        for (int nt = 0; nt < 4; ++nt)
            #pragma unroll
            for (int i = 0; i < 4; ++i) { C1[mt][nt][i] = 0; Cx[mt][nt][i] = 0; }

    load_stage(0);

    for (int c = 0; c < NCHUNK; ++c) {
        CP_WAIT0();
        __syncthreads();
        if (c + 1 < NCHUNK) load_stage(c + 1);

        const uint32_t sb = sb0 + (c & 1) * STAGE;

        #pragma unroll
        for (int kk0 = 0; kk0 < NKK; ++kk0) {
            // per-warp kk rotation: de-phases LDSM/IMMA bursts across warps.
            // Integer accumulation is exact => order-independent, bit-identical.
            const int kk = (kk0 + wid) & (NKK - 1);
            const uint32_t ab = sb + (uint32_t)(a_row * ROWB + kk * 32 + a_kby);
            const uint32_t bb = sb + (uint32_t)(b_row * ROWB + kk * 32 + b_kby);

            uint32_t aF[2][4], bF[2][4], bG[2][4];

            #pragma unroll
            for (int mt = 0; mt < 2; ++mt) ldm_x4(aF[mt], ab + OFF_A1 + mt * 16 * ROWB);
            #pragma unroll
            for (int ne = 0; ne < 2; ++ne) ldm_x4(bF[ne], bb + OFF_B1 + ne * 16 * ROWB);
            #pragma unroll
            for (int ne = 0; ne < 2; ++ne) ldm_x4(bG[ne], bb + OFF_B2 + ne * 16 * ROWB);

            // pass 1: A1*B1 -> C1
            #pragma unroll
            for (int mt = 0; mt < 2; ++mt)
                #pragma unroll
                for (int nt = 0; nt < 4; ++nt) {
                    const int ne = nt >> 1, h2 = (nt & 1) * 2;
                    IMMA(C1[mt][nt], aF[mt], bF[ne][h2], bF[ne][h2 + 1]);
                }
            // pass 2: A1*B2 -> Cx
            #pragma unroll
            for (int mt = 0; mt < 2; ++mt)
                #pragma unroll
                for (int nt = 0; nt < 4; ++nt) {
                    const int ne = nt >> 1, h2 = (nt & 1) * 2;
                    IMMA(Cx[mt][nt], aF[mt], bG[ne][h2], bG[ne][h2 + 1]);
                }
            // A2 loads, then pass 3: A2*B1 -> Cx
            #pragma unroll
            for (int mt = 0; mt < 2; ++mt) ldm_x4(aF[mt], ab + OFF_A2 + mt * 16 * ROWB);
            #pragma unroll
            for (int mt = 0; mt < 2; ++mt)
                #pragma unroll
                for (int nt = 0; nt < 4; ++nt) {
                    const int ne = nt >> 1, h2 = (nt & 1) * 2;
                    IMMA(Cx[mt][nt], aF[mt], bF[ne][h2], bF[ne][h2 + 1]);
                }
        }
    }

    // ---------------- Epilogue ----------------
    float o0s[2][2], o1s[2][2];
    if constexpr (EPI == 2) {
        #pragma unroll
        for (int mt = 0; mt < 2; ++mt) { o0s[mt][0] = o0s[mt][1] = 0.f;
                                         o1s[mt][0] = o1s[mt][1] = 0.f; }
    }

    #pragma unroll
    for (int mt = 0; mt < 2; ++mt) {
        const int r0 = rowBase + warp_m * 32 + mt * 16 + g;
        const float sa0 = sA ? sA[r0] : sAc;
        const float sa1 = sA ? sA[r0 + 8] : sAc;
        float xn0 = 0.f, xn1 = 0.f;
        if (EPI == 0) { xn0 = g_xn[r0]; xn1 = g_xn[r0 + 8]; }

        #pragma unroll
        for (int nt = 0; nt < 4; ++nt) {
            const int cidx = colBase + warp_n * 32 + nt * 8 + 2 * tg;
            const float q0 = sB[cidx] * INVQ, q1 = sB[cidx + 1] * INVQ;
            float d00 = ((float)C1[mt][nt][0] + (float)Cx[mt][nt][0] * INV254) * (sa0 * q0);
            float d01 = ((float)C1[mt][nt][1] + (float)Cx[mt][nt][1] * INV254) * (sa0 * q1);
            float d10 = ((float)C1[mt][nt][2] + (float)Cx[mt][nt][2] * INV254) * (sa1 * q0);
            float d11 = ((float)C1[mt][nt][3] + (float)Cx[mt][nt][3] * INV254) * (sa1 * q1);

            if constexpr (EPI == 0) {
                float sn0 = g_svn[cidx], sn1 = g_svn[cidx + 1];
                float k00 = __expf(GAMMA_F * (2.f * d00 - xn0 - sn0));
                float k01 = __expf(GAMMA_F * (2.f * d01 - xn0 - sn1));
                float k10 = __expf(GAMMA_F * (2.f * d10 - xn1 - sn0));
                float k11 = __expf(GAMMA_F * (2.f * d11 - xn1 - sn1));
                char2 p1, p2;
                size_t o0 = (size_t)r0 * S_DIM + cidx;
                size_t o1 = (size_t)(r0 + 8) * S_DIM + cidx;
                qpair(k00, 127.0f, (int8_t&)p1.x, (int8_t&)p2.x);
                qpair(k01, 127.0f, (int8_t&)p1.y, (int8_t&)p2.y);
                *(char2*)(g_ka + o0) = p1; *(char2*)(g_kb + o0) = p2;
                qpair(k10, 127.0f, (int8_t&)p1.x, (int8_t&)p2.x);
                qpair(k11, 127.0f, (int8_t&)p1.y, (int8_t&)p2.y);
                *(char2*)(g_ka + o1) = p1; *(char2*)(g_kb + o1) = p2;
            } else if constexpr (EPI == 1) {
                const float invh = 127.0f / H_SCALE;
                float b0v = bias[cidx], b1v = bias[cidx + 1];
                float h00 = fmaxf(d00 + b0v, 0.f), h01 = fmaxf(d01 + b1v, 0.f);
                float h10 = fmaxf(d10 + b0v, 0.f), h11 = fmaxf(d11 + b1v, 0.f);
                char2 p1, p2;
                size_t o0 = (size_t)r0 * S_DIM + cidx;
                size_t o1 = (size_t)(r0 + 8) * S_DIM + cidx;
                qpair(h00, invh, (int8_t&)p1.x, (int8_t&)p2.x);
                qpair(h01, invh, (int8_t&)p1.y, (int8_t&)p2.y);
                *(char2*)(g_ha + o0) = p1; *(char2*)(g_hb + o0) = p2;
                qpair(h10, invh, (int8_t&)p1.x, (int8_t&)p2.x);
                qpair(h11, invh, (int8_t&)p1.y, (int8_t&)p2.y);
                *(char2*)(g_ha + o1) = p1; *(char2*)(g_hb + o1) = p2;
            } else {
                float b0v = bias[cidx], b1v = bias[cidx + 1];
                float w00 = Wh[cidx],         w01 = Wh[cidx + 1];
                float w10 = Wh[S_DIM + cidx], w11 = Wh[S_DIM + cidx + 1];
                float v00 = fmaxf(d00 + b0v, 0.f), v01 = fmaxf(d01 + b1v, 0.f);
                float v10 = fmaxf(d10 + b0v, 0.f), v11 = fmaxf(d11 + b1v, 0.f);
                o0s[mt][0] = fmaf(v00, w00, fmaf(v01, w01, o0s[mt][0]));
                o1s[mt][0] = fmaf(v00, w10, fmaf(v01, w11, o1s[mt][0]));
                o0s[mt][1] = fmaf(v10, w00, fmaf(v11, w01, o0s[mt][1]));
                o1s[mt][1] = fmaf(v10, w10, fmaf(v11, w11, o1s[mt][1]));
            }
        }
    }

    if constexpr (EPI == 2) {
        #pragma unroll
        for (int mt = 0; mt < 2; ++mt)
            #pragma unroll
            for (int rh = 0; rh < 2; ++rh) {
                float a = o0s[mt][rh], b = o1s[mt][rh];
                a += __shfl_xor_sync(0xffffffffu, a, 1);
                a += __shfl_xor_sync(0xffffffffu, a, 2);
                b += __shfl_xor_sync(0xffffffffu, b, 1);
                b += __shfl_xor_sync(0xffffffffu, b, 2);
                o0s[mt][rh] = a; o1s[mt][rh] = b;
            }
        if (tg == 0) {
            int slot = blockIdx.x * 4 + warp_n;   // 0..31
            #pragma unroll
            for (int mt = 0; mt < 2; ++mt)
                #pragma unroll
                for (int rh = 0; rh < 2; ++rh) {
                    int row = rowBase + warp_m * 32 + mt * 16 + g + rh * 8;
                    size_t base = ((size_t)slot * B_ROWS + row) * 2;
                    g_part[base]     = o0s[mt][rh];
                    g_part[base + 1] = o1s[mt][rh];
                }
        }
    }
}

// ============================================================================
// Head reduction
// ============================================================================
__global__ void head_final(const float* __restrict__ bh, float* __restrict__ out) {
    int i = blockIdx.x * blockDim.x + threadIdx.x;
    if (i < B_ROWS * 2) {
        float s = bh[i & 1];
        #pragma unroll
        for (int t = 0; t < 32; ++t) s += g_part[(size_t)t * B_ROWS * 2 + i];
        out[i] = s;
    }
}

// ============================================================================
// Launcher — GEMM1/GEMM2 at launch indices 3/4 (ncu capture window)
// ============================================================================
extern "C" void kernel_launch(void* const* d_in, const int* in_sizes, int n_in,
                              void* d_out, int out_size) {
    (void)in_sizes; (void)n_in; (void)out_size;
    const float* x  = (const float*)d_in[0];
    const float* sv = (const float*)d_in[1];
    const float* W1 = (const float*)d_in[2];
    const float* b1 = (const float*)d_in[3];
    const float* W2 = (const float*)d_in[4];
    const float* b2 = (const float*)d_in[5];
    const float* Wh = (const float*)d_in[6];
    const float* bh = (const float*)d_in[7];
    float* out = (float*)d_out;

    static int8_t *xa, *xb, *sva, *svb, *w1a, *w1b, *w2a, *w2b, *ka, *kb, *ha, *hb;
    static float *xs, *svs, *w1s, *w2s, *xn, *svn;
    static bool got = false;
    if (!got) {
        cudaGetSymbolAddress((void**)&xa,  g_xa);  cudaGetSymbolAddress((void**)&xb,  g_xb);
        cudaGetSymbolAddress((void**)&sva, g_sva); cudaGetSymbolAddress((void**)&svb, g_svb);
        cudaGetSymbolAddress((void**)&w1a, g_w1a); cudaGetSymbolAddress((void**)&w1b, g_w1b);
        cudaGetSymbolAddress((void**)&w2a, g_w2a); cudaGetSymbolAddress((void**)&w2b, g_w2b);
        cudaGetSymbolAddress((void**)&ka,  g_ka);  cudaGetSymbolAddress((void**)&kb,  g_kb);
        cudaGetSymbolAddress((void**)&ha,  g_ha);  cudaGetSymbolAddress((void**)&hb,  g_hb);
        cudaGetSymbolAddress((void**)&xs,  g_xs);  cudaGetSymbolAddress((void**)&svs, g_svs);
        cudaGetSymbolAddress((void**)&w1s, g_w1s); cudaGetSymbolAddress((void**)&w2s, g_w2s);
        cudaGetSymbolAddress((void**)&xn,  g_xn);  cudaGetSymbolAddress((void**)&svn, g_svn);
        cudaFuncSetAttribute((const void*)gemm_i8<FEAT, 64, 0>,
                             cudaFuncAttributeMaxDynamicSharedMemorySize, SMEM_G1);
        cudaFuncSetAttribute((const void*)gemm_i8<S_DIM, 128, 1>,
                             cudaFuncAttributeMaxDynamicSharedMemorySize, SMEM_G2);
        cudaFuncSetAttribute((const void*)gemm_i8<S_DIM, 128, 2>,
                             cudaFuncAttributeMaxDynamicSharedMemorySize, SMEM_G2);
        got = true;
    }

    dim3 grid(S_DIM / BN, B_ROWS / BM);   // (8, 1024)

    // idx 0-2: quantize x (+norm), sv (+norm), W1
    quant_rows<FEAT, true ><<<B_ROWS / 8, 256>>>(x,  xa,  xb,  xs,  xn);
    quant_rows<FEAT, true ><<<S_DIM  / 8, 256>>>(sv, sva, svb, svs, svn);
    quant_rows<S_DIM, false><<<S_DIM / 8, 256>>>(W1, w1a, w1b, w1s, nullptr);
    // idx 3: GEMM1 (RBF features -> int8 k, scale 1), BK=64 -> 4-chunk pipeline
    gemm_i8<FEAT, 64, 0><<<grid, NTH, SMEM_G1>>>(xa, xb, sva, svb, xs, 1.0f, svs,
                                                 nullptr, nullptr);
    // idx 4: GEMM2 (hidden1 -> int8 h, fixed scale H_SCALE; fused quant)
    gemm_i8<S_DIM, 128, 1><<<grid, NTH, SMEM_G2>>>(ka, kb, w1a, w1b, nullptr, 1.0f, w1s,
                                                   b1, nullptr);
    // idx 5: quantize W2
    quant_rows<S_DIM, false><<<S_DIM / 8, 256>>>(W2, w2a, w2b, w2s, nullptr);
    // idx 6: GEMM3 (hidden2 + head partials; A-scale = H_SCALE constant)
    gemm_i8<S_DIM, 128, 2><<<grid, NTH, SMEM_G2>>>(ha, hb, w2a, w2b, nullptr, H_SCALE, w2s,
                                                   b2, Wh);
    // idx 7: head reduction
    head_final<<<(B_ROWS * 2 + 255) / 256, 256>>>(bh, out);
}

// round 11
// speedup vs baseline: 1.0249x; 1.0249x over previous
#include <cuda_runtime.h>
#include <cstdint>

// ============================================================================
// Problem constants
// ============================================================================
#define GAMMA_F 0.00390625f

constexpr int B_ROWS = 65536;
constexpr int FEAT   = 256;
constexpr int S_DIM  = 1024;

constexpr int BM  = 64;
constexpr int BN  = 128;
constexpr int NTH = 256;

constexpr float INV254 = 1.0f / 254.0f;
constexpr float INVQ   = 1.0f / 16129.0f;   // 1/127^2
constexpr float H_SCALE = 1.25f;            // fixed quant scale for hidden h

constexpr int stage_bytes(int bk) { return 2 * BM * (bk + 16) + 2 * BN * (bk + 16); }
constexpr int SMEM_G1 = stage_bytes(256);        // 104448, single stage, 2 CTAs/SM
constexpr int SMEM_G2 = 2 * stage_bytes(128);    // 110592, double buffer, 2 CTAs/SM

// ============================================================================
// Device scratch (__device__ globals: alloc-free rule)
// ============================================================================
__device__ __align__(16) int8_t g_xa [(size_t)B_ROWS * FEAT];
__device__ __align__(16) int8_t g_xb [(size_t)B_ROWS * FEAT];
__device__ __align__(16) int8_t g_sva[(size_t)S_DIM * FEAT];
__device__ __align__(16) int8_t g_svb[(size_t)S_DIM * FEAT];
__device__ __align__(16) int8_t g_w1a[(size_t)S_DIM * S_DIM];
__device__ __align__(16) int8_t g_w1b[(size_t)S_DIM * S_DIM];
__device__ __align__(16) int8_t g_w2a[(size_t)S_DIM * S_DIM];
__device__ __align__(16) int8_t g_w2b[(size_t)S_DIM * S_DIM];
__device__ __align__(16) int8_t g_ka [(size_t)B_ROWS * S_DIM];
__device__ __align__(16) int8_t g_kb [(size_t)B_ROWS * S_DIM];
__device__ __align__(16) int8_t g_ha [(size_t)B_ROWS * S_DIM];
__device__ __align__(16) int8_t g_hb [(size_t)B_ROWS * S_DIM];
__device__ float g_xs [B_ROWS];
__device__ float g_svs[S_DIM];
__device__ float g_w1s[S_DIM];
__device__ float g_w2s[S_DIM];
__device__ float g_xn [B_ROWS];
__device__ float g_svn[S_DIM];
__device__ float g_part[32 * B_ROWS * 2];

// ============================================================================
// PTX helpers
// ============================================================================
__device__ __forceinline__ uint32_t smem_u32(const void* p) {
    uint32_t a;
    asm("{ .reg .u64 t; cvta.to.shared.u64 t, %1; cvt.u32.u64 %0, t; }"
        : "=r"(a) : "l"(p));
    return a;
}

__device__ __forceinline__ void cp16(uint32_t s, const void* g) {
    asm volatile("cp.async.cg.shared.global [%0], [%1], 16;"
                 :: "r"(s), "l"((unsigned long long)(uintptr_t)g) : "memory");
}
#define CP_COMMIT()  asm volatile("cp.async.commit_group;" ::: "memory")
#define CP_WAIT0()   asm volatile("cp.async.wait_group 0;" ::: "memory")

__device__ __forceinline__ void ldm_x4(uint32_t* r, uint32_t saddr) {
    asm volatile("ldmatrix.sync.aligned.m8n8.x4.shared.b16 {%0,%1,%2,%3}, [%4];"
                 : "=r"(r[0]), "=r"(r[1]), "=r"(r[2]), "=r"(r[3]) : "r"(saddr));
}

#define IMMA(C, A, B0, B1)                                                     \
    asm volatile(                                                              \
        "mma.sync.aligned.m16n8k32.row.col.s32.s8.s8.s32 "                     \
        "{%0,%1,%2,%3}, {%4,%5,%6,%7}, {%8,%9}, {%0,%1,%2,%3};"                \
        : "+r"((C)[0]), "+r"((C)[1]), "+r"((C)[2]), "+r"((C)[3])               \
        : "r"((A)[0]), "r"((A)[1]), "r"((A)[2]), "r"((A)[3]),                  \
          "r"(B0), "r"(B1))

// fp32 -> 2-slice int8 (inv = 127/scale), clamped
__device__ __forceinline__ void qpair(float v, float inv, int8_t& o1, int8_t& o2) {
    float q = fminf(fmaxf(v * inv, -127.0f), 127.0f);
    float R = rintf(q);
    o1 = (int8_t)(int)R;
    o2 = (int8_t)(int)rintf((q - R) * 254.0f);
}

// ============================================================================
// Row-wise 2-slice quantizer (warp per row)
// ============================================================================
template <int COLS, bool NORM>
__global__ void quant_rows(const float* __restrict__ src,
                           int8_t* __restrict__ q1, int8_t* __restrict__ q2,
                           float* __restrict__ sOut, float* __restrict__ nrm) {
    int row  = blockIdx.x * 8 + (threadIdx.x >> 5);
    int lane = threadIdx.x & 31;
    const float4* s4 = (const float4*)(src + (size_t)row * COLS);
    float4 vb[COLS / 128];
    float mx = 0.f, ss = 0.f;
    #pragma unroll
    for (int i = 0; i < COLS / 128; ++i) {
        float4 v = s4[i * 32 + lane];
        vb[i] = v;
        mx = fmaxf(mx, fmaxf(fmaxf(fabsf(v.x), fabsf(v.y)),
                             fmaxf(fabsf(v.z), fabsf(v.w))));
        if (NORM)
            ss = fmaf(v.x, v.x, fmaf(v.y, v.y, fmaf(v.z, v.z, fmaf(v.w, v.w, ss))));
    }
    #pragma unroll
    for (int o = 16; o; o >>= 1) {
        mx = fmaxf(mx, __shfl_xor_sync(0xffffffffu, mx, o));
        if (NORM) ss += __shfl_xor_sync(0xffffffffu, ss, o);
    }
    float s = mx > 0.f ? mx : 1.0f;
    if (lane == 0) {
        sOut[row] = s;
        if (NORM) nrm[row] = ss;
    }
    float inv = 127.0f / s;
    #pragma unroll
    for (int i = 0; i < COLS / 128; ++i) {
        char4 c1, c2;
        qpair(vb[i].x, inv, (int8_t&)c1.x, (int8_t&)c2.x);
        qpair(vb[i].y, inv, (int8_t&)c1.y, (int8_t&)c2.y);
        qpair(vb[i].z, inv, (int8_t&)c1.z, (int8_t&)c2.z);
        qpair(vb[i].w, inv, (int8_t&)c1.w, (int8_t&)c2.w);
        size_t o = (size_t)row * COLS + i * 128 + lane * 4;
        *(char4*)(q1 + o) = c1;
        *(char4*)(q2 + o) = c2;
    }
}

// ============================================================================
// Int8 2-slice GEMM (templated BK; single-stage when BKT==KTOT).
//  D[m,n] = sum_k A[m,k] * B[n,k]
//  dot = (C1 + Cx/254) * sA*sB/127^2,  C1 = A1B1, Cx = A1B2 + A2B1
//  EPI 0: k = exp(g*(2*dot - xn - svn)) -> g_ka/g_kb (scale 1)
//  EPI 1: h = relu(dot + b1)            -> g_ha/g_hb (fixed scale H_SCALE)
//  EPI 2: v = relu(dot + b2); head partials -> g_part
// ============================================================================
template <int KTOT, int BKT, int EPI>
__global__ void __launch_bounds__(NTH, 2)
gemm_i8(const int8_t* __restrict__ A1p, const int8_t* __restrict__ A2p,
        const int8_t* __restrict__ B1p, const int8_t* __restrict__ B2p,
        const float* __restrict__ sA, float sAc, const float* __restrict__ sB,
        const float* __restrict__ bias, const float* __restrict__ Wh) {
    constexpr int ROWB    = BKT + 16;
    constexpr int A_PLANE = BM * ROWB;
    constexpr int B_PLANE = BN * ROWB;
    constexpr int OFF_A1  = 0;
    constexpr int OFF_A2  = A_PLANE;
    constexpr int OFF_B1  = 2 * A_PLANE;
    constexpr int OFF_B2  = 2 * A_PLANE + B_PLANE;
    constexpr int STAGE   = 2 * A_PLANE + 2 * B_PLANE;
    constexpr int NKK     = BKT / 32;
    constexpr int NCHUNK  = KTOT / BKT;

    extern __shared__ char smem[];
    const uint32_t sb0 = smem_u32(smem);

    const int tid    = threadIdx.x;
    const int wid    = tid >> 5;
    const int lane   = tid & 31;
    const int g      = lane >> 2;
    const int tg     = lane & 3;
    const int warp_m = wid & 1;         // 0..1  (32-row halves)
    const int warp_n = wid >> 1;        // 0..3  (32-col slices)

    const int rowBase = blockIdx.y * BM;
    const int colBase = blockIdx.x * BN;

    const int a_row = warp_m * 32 + (lane & 7) + ((lane >> 3) & 1) * 8;
    const int a_kby = (lane >> 4) * 16;
    const int b_row = warp_n * 32 + (lane & 7) + (lane >> 4) * 8;
    const int b_kby = ((lane >> 3) & 1) * 16;

    auto load_stage = [&](int c) {
        uint32_t s0 = sb0 + (NCHUNK > 1 ? (c & 1) * STAGE : 0);
        const int kc = c * BKT;
        constexpr int SEG = BKT / 16;
        #pragma unroll
        for (int u = tid; u < BM * SEG; u += NTH) {
            int row = u / SEG, seg = u % SEG;
            size_t go = (size_t)(rowBase + row) * KTOT + kc + seg * 16;
            cp16(s0 + OFF_A1 + row * ROWB + seg * 16, A1p + go);
            cp16(s0 + OFF_A2 + row * ROWB + seg * 16, A2p + go);
        }
        #pragma unroll
        for (int u = tid; u < BN * SEG; u += NTH) {
            int row = u / SEG, seg = u % SEG;
            size_t go = (size_t)(colBase + row) * KTOT + kc + seg * 16;
            cp16(s0 + OFF_B1 + row * ROWB + seg * 16, B1p + go);
            cp16(s0 + OFF_B2 + row * ROWB + seg * 16, B2p + go);
        }
        CP_COMMIT();
    };

    int C1[2][4][4], Cx[2][4][4];
    #pragma unroll
    for (int mt = 0; mt < 2; ++mt)
        #pragma unroll
        for (int nt = 0; nt < 4; ++nt)
            #pragma unroll
            for (int i = 0; i < 4; ++i) { C1[mt][nt][i] = 0; Cx[mt][nt][i] = 0; }

    load_stage(0);

    for (int c = 0; c < NCHUNK; ++c) {
        CP_WAIT0();
        __syncthreads();
        if (c + 1 < NCHUNK) load_stage(c + 1);

        const uint32_t sb = sb0 + (NCHUNK > 1 ? (c & 1) * STAGE : 0);

        #pragma unroll
        for (int kk = 0; kk < NKK; ++kk) {
            const uint32_t ab = sb + (uint32_t)(a_row * ROWB + kk * 32 + a_kby);
            const uint32_t bb = sb + (uint32_t)(b_row * ROWB + kk * 32 + b_kby);

            uint32_t aF[2][4], bF[2][4], bG[2][4];

            #pragma unroll
            for (int mt = 0; mt < 2; ++mt) ldm_x4(aF[mt], ab + OFF_A1 + mt * 16 * ROWB);
            #pragma unroll
            for (int ne = 0; ne < 2; ++ne) ldm_x4(bF[ne], bb + OFF_B1 + ne * 16 * ROWB);
            #pragma unroll
            for (int ne = 0; ne < 2; ++ne) ldm_x4(bG[ne], bb + OFF_B2 + ne * 16 * ROWB);

            // pass 1: A1*B1 -> C1
            #pragma unroll
            for (int mt = 0; mt < 2; ++mt)
                #pragma unroll
                for (int nt = 0; nt < 4; ++nt) {
                    const int ne = nt >> 1, h2 = (nt & 1) * 2;
                    IMMA(C1[mt][nt], aF[mt], bF[ne][h2], bF[ne][h2 + 1]);
                }
            // pass 2: A1*B2 -> Cx
            #pragma unroll
            for (int mt = 0; mt < 2; ++mt)
                #pragma unroll
                for (int nt = 0; nt < 4; ++nt) {
                    const int ne = nt >> 1, h2 = (nt & 1) * 2;
                    IMMA(Cx[mt][nt], aF[mt], bG[ne][h2], bG[ne][h2 + 1]);
                }
            // A2 loads (reuse aF regs), then pass 3: A2*B1 -> Cx
            #pragma unroll
            for (int mt = 0; mt < 2; ++mt) ldm_x4(aF[mt], ab + OFF_A2 + mt * 16 * ROWB);
            #pragma unroll
            for (int mt = 0; mt < 2; ++mt)
                #pragma unroll
                for (int nt = 0; nt < 4; ++nt) {
                    const int ne = nt >> 1, h2 = (nt & 1) * 2;
                    IMMA(Cx[mt][nt], aF[mt], bF[ne][h2], bF[ne][h2 + 1]);
                }
        }
    }

    // ---------------- Epilogue ----------------
    float o0s[2][2], o1s[2][2];
    if constexpr (EPI == 2) {
        #pragma unroll
        for (int mt = 0; mt < 2; ++mt) { o0s[mt][0] = o0s[mt][1] = 0.f;
                                         o1s[mt][0] = o1s[mt][1] = 0.f; }
    }

    #pragma unroll
    for (int mt = 0; mt < 2; ++mt) {
        const int r0 = rowBase + warp_m * 32 + mt * 16 + g;
        const float sa0 = sA ? sA[r0] : sAc;
        const float sa1 = sA ? sA[r0 + 8] : sAc;
        float xn0 = 0.f, xn1 = 0.f;
        if (EPI == 0) { xn0 = g_xn[r0]; xn1 = g_xn[r0 + 8]; }

        #pragma unroll
        for (int nt = 0; nt < 4; ++nt) {
            const int cidx = colBase + warp_n * 32 + nt * 8 + 2 * tg;
            const float q0 = sB[cidx] * INVQ, q1 = sB[cidx + 1] * INVQ;
            float d00 = ((float)C1[mt][nt][0] + (float)Cx[mt][nt][0] * INV254) * (sa0 * q0);
            float d01 = ((float)C1[mt][nt][1] + (float)Cx[mt][nt][1] * INV254) * (sa0 * q1);
            float d10 = ((float)C1[mt][nt][2] + (float)Cx[mt][nt][2] * INV254) * (sa1 * q0);
            float d11 = ((float)C1[mt][nt][3] + (float)Cx[mt][nt][3] * INV254) * (sa1 * q1);

            if constexpr (EPI == 0) {
                float sn0 = g_svn[cidx], sn1 = g_svn[cidx + 1];
                float k00 = __expf(GAMMA_F * (2.f * d00 - xn0 - sn0));
                float k01 = __expf(GAMMA_F * (2.f * d01 - xn0 - sn1));
                float k10 = __expf(GAMMA_F * (2.f * d10 - xn1 - sn0));
                float k11 = __expf(GAMMA_F * (2.f * d11 - xn1 - sn1));
                char2 p1, p2;
                size_t o0 = (size_t)r0 * S_DIM + cidx;
                size_t o1 = (size_t)(r0 + 8) * S_DIM + cidx;
                qpair(k00, 127.0f, (int8_t&)p1.x, (int8_t&)p2.x);
                qpair(k01, 127.0f, (int8_t&)p1.y, (int8_t&)p2.y);
                *(char2*)(g_ka + o0) = p1; *(char2*)(g_kb + o0) = p2;
                qpair(k10, 127.0f, (int8_t&)p1.x, (int8_t&)p2.x);
                qpair(k11, 127.0f, (int8_t&)p1.y, (int8_t&)p2.y);
                *(char2*)(g_ka + o1) = p1; *(char2*)(g_kb + o1) = p2;
            } else if constexpr (EPI == 1) {
                const float invh = 127.0f / H_SCALE;
                float b0v = bias[cidx], b1v = bias[cidx + 1];
                float h00 = fmaxf(d00 + b0v, 0.f), h01 = fmaxf(d01 + b1v, 0.f);
                float h10 = fmaxf(d10 + b0v, 0.f), h11 = fmaxf(d11 + b1v, 0.f);
                char2 p1, p2;
                size_t o0 = (size_t)r0 * S_DIM + cidx;
                size_t o1 = (size_t)(r0 + 8) * S_DIM + cidx;
                qpair(h00, invh, (int8_t&)p1.x, (int8_t&)p2.x);
                qpair(h01, invh, (int8_t&)p1.y, (int8_t&)p2.y);
                *(char2*)(g_ha + o0) = p1; *(char2*)(g_hb + o0) = p2;
                qpair(h10, invh, (int8_t&)p1.x, (int8_t&)p2.x);
                qpair(h11, invh, (int8_t&)p1.y, (int8_t&)p2.y);
                *(char2*)(g_ha + o1) = p1; *(char2*)(g_hb + o1) = p2;
            } else {
                float b0v = bias[cidx], b1v = bias[cidx + 1];
                float w00 = Wh[cidx],         w01 = Wh[cidx + 1];
                float w10 = Wh[S_DIM + cidx], w11 = Wh[S_DIM + cidx + 1];
                float v00 = fmaxf(d00 + b0v, 0.f), v01 = fmaxf(d01 + b1v, 0.f);
                float v10 = fmaxf(d10 + b0v, 0.f), v11 = fmaxf(d11 + b1v, 0.f);
                o0s[mt][0] = fmaf(v00, w00, fmaf(v01, w01, o0s[mt][0]));
                o1s[mt][0] = fmaf(v00, w10, fmaf(v01, w11, o1s[mt][0]));
                o0s[mt][1] = fmaf(v10, w00, fmaf(v11, w01, o0s[mt][1]));
                o1s[mt][1] = fmaf(v10, w10, fmaf(v11, w11, o1s[mt][1]));
            }
        }
    }

    if constexpr (EPI == 2) {
        #pragma unroll
        for (int mt = 0; mt < 2; ++mt)
            #pragma unroll
            for (int rh = 0; rh < 2; ++rh) {
                float a = o0s[mt][rh], b = o1s[mt][rh];
                a += __shfl_xor_sync(0xffffffffu, a, 1);
                a += __shfl_xor_sync(0xffffffffu, a, 2);
                b += __shfl_xor_sync(0xffffffffu, b, 1);
                b += __shfl_xor_sync(0xffffffffu, b, 2);
                o0s[mt][rh] = a; o1s[mt][rh] = b;
            }
        if (tg == 0) {
            int slot = blockIdx.x * 4 + warp_n;   // 0..31
            #pragma unroll
            for (int mt = 0; mt < 2; ++mt)
                #pragma unroll
                for (int rh = 0; rh < 2; ++rh) {
                    int row = rowBase + warp_m * 32 + mt * 16 + g + rh * 8;
                    size_t base = ((size_t)slot * B_ROWS + row) * 2;
                    g_part[base]     = o0s[mt][rh];
                    g_part[base + 1] = o1s[mt][rh];
                }
        }
    }
}

// ============================================================================
// Head reduction
// ============================================================================
__global__ void head_final(const float* __restrict__ bh, float* __restrict__ out) {
    int i = blockIdx.x * blockDim.x + threadIdx.x;
    if (i < B_ROWS * 2) {
        float s = bh[i & 1];
        #pragma unroll
        for (int t = 0; t < 32; ++t) s += g_part[(size_t)t * B_ROWS * 2 + i];
        out[i] = s;
    }
}

// ============================================================================
// Launcher — GEMM1/GEMM2 at launch indices 3/4 (ncu capture window)
// ============================================================================
extern "C" void kernel_launch(void* const* d_in, const int* in_sizes, int n_in,
                              void* d_out, int out_size) {
    (void)in_sizes; (void)n_in; (void)out_size;
    const float* x  = (const float*)d_in[0];
    const float* sv = (const float*)d_in[1];
    const float* W1 = (const float*)d_in[2];
    const float* b1 = (const float*)d_in[3];
    const float* W2 = (const float*)d_in[4];
    const float* b2 = (const float*)d_in[5];
    const float* Wh = (const float*)d_in[6];
    const float* bh = (const float*)d_in[7];
    float* out = (float*)d_out;

    static int8_t *xa, *xb, *sva, *svb, *w1a, *w1b, *w2a, *w2b, *ka, *kb, *ha, *hb;
    static float *xs, *svs, *w1s, *w2s, *xn, *svn;
    static bool got = false;
    if (!got) {
        cudaGetSymbolAddress((void**)&xa,  g_xa);  cudaGetSymbolAddress((void**)&xb,  g_xb);
        cudaGetSymbolAddress((void**)&sva, g_sva); cudaGetSymbolAddress((void**)&svb, g_svb);
        cudaGetSymbolAddress((void**)&w1a, g_w1a); cudaGetSymbolAddress((void**)&w1b, g_w1b);
        cudaGetSymbolAddress((void**)&w2a, g_w2a); cudaGetSymbolAddress((void**)&w2b, g_w2b);
        cudaGetSymbolAddress((void**)&ka,  g_ka);  cudaGetSymbolAddress((void**)&kb,  g_kb);
        cudaGetSymbolAddress((void**)&ha,  g_ha);  cudaGetSymbolAddress((void**)&hb,  g_hb);
        cudaGetSymbolAddress((void**)&xs,  g_xs);  cudaGetSymbolAddress((void**)&svs, g_svs);
        cudaGetSymbolAddress((void**)&w1s, g_w1s); cudaGetSymbolAddress((void**)&w2s, g_w2s);
        cudaGetSymbolAddress((void**)&xn,  g_xn);  cudaGetSymbolAddress((void**)&svn, g_svn);
        cudaFuncSetAttribute((const void*)gemm_i8<FEAT, 256, 0>,
                             cudaFuncAttributeMaxDynamicSharedMemorySize, SMEM_G1);
        cudaFuncSetAttribute((const void*)gemm_i8<S_DIM, 128, 1>,
                             cudaFuncAttributeMaxDynamicSharedMemorySize, SMEM_G2);
        cudaFuncSetAttribute((const void*)gemm_i8<S_DIM, 128, 2>,
                             cudaFuncAttributeMaxDynamicSharedMemorySize, SMEM_G2);
        got = true;
    }

    dim3 grid(S_DIM / BN, B_ROWS / BM);   // (8, 1024)

    // idx 0-2: quantize x (+norm), sv (+norm), W1
    quant_rows<FEAT, true ><<<B_ROWS / 8, 256>>>(x,  xa,  xb,  xs,  xn);
    quant_rows<FEAT, true ><<<S_DIM  / 8, 256>>>(sv, sva, svb, svs, svn);
    quant_rows<S_DIM, false><<<S_DIM / 8, 256>>>(W1, w1a, w1b, w1s, nullptr);
    // idx 3: GEMM1 (RBF features -> int8 k, scale 1), single-stage BK=256
    gemm_i8<FEAT, 256, 0><<<grid, NTH, SMEM_G1>>>(xa, xb, sva, svb, xs, 1.0f, svs,
                                                  nullptr, nullptr);
    // idx 4: GEMM2 (hidden1 -> int8 h, fixed scale H_SCALE; fused quant)
    gemm_i8<S_DIM, 128, 1><<<grid, NTH, SMEM_G2>>>(ka, kb, w1a, w1b, nullptr, 1.0f, w1s,
                                                   b1, nullptr);
    // idx 5: quantize W2
    quant_rows<S_DIM, false><<<S_DIM / 8, 256>>>(W2, w2a, w2b, w2s, nullptr);
    // idx 6: GEMM3 (hidden2 + head partials; A-scale = H_SCALE constant)
    gemm_i8<S_DIM, 128, 2><<<grid, NTH, SMEM_G2>>>(ha, hb, w2a, w2b, nullptr, H_SCALE, w2s,
                                                   b2, Wh);
    // idx 7: head reduction
    head_final<<<(B_ROWS * 2 + 255) / 256, 256>>>(bh, out);
}

// round 12
// speedup vs baseline: 1.0526x; 1.0270x over previous
#include <cuda_runtime.h>
#include <cstdint>

// ============================================================================
// Problem constants
// ============================================================================
#define GAMMA_F 0.00390625f

constexpr int B_ROWS = 65536;
constexpr int FEAT   = 256;
constexpr int S_DIM  = 1024;

constexpr int BM  = 64;
constexpr int BN  = 128;
constexpr int NTH = 256;

constexpr float INV254 = 1.0f / 254.0f;
constexpr float INVQ   = 1.0f / 16129.0f;   // 1/127^2
constexpr float H_SCALE = 1.25f;            // fixed quant scale for hidden h

constexpr int stage_bytes(int bk) { return 2 * BM * (bk + 16) + 2 * BN * (bk + 16); }
constexpr int SMEM_G2 = 2 * stage_bytes(128);    // 110592, double buffer, 2 CTAs/SM
constexpr int SMEM_G1 = 110592;                   // persistent G1: B 73728 + A 36864

// ============================================================================
// Device scratch (__device__ globals: alloc-free rule)
// ============================================================================
__device__ __align__(16) int8_t g_xa [(size_t)B_ROWS * FEAT];
__device__ __align__(16) int8_t g_xb [(size_t)B_ROWS * FEAT];
__device__ __align__(16) int8_t g_sva[(size_t)S_DIM * FEAT];
__device__ __align__(16) int8_t g_svb[(size_t)S_DIM * FEAT];
__device__ __align__(16) int8_t g_w1a[(size_t)S_DIM * S_DIM];
__device__ __align__(16) int8_t g_w1b[(size_t)S_DIM * S_DIM];
__device__ __align__(16) int8_t g_w2a[(size_t)S_DIM * S_DIM];
__device__ __align__(16) int8_t g_w2b[(size_t)S_DIM * S_DIM];
__device__ __align__(16) int8_t g_ka [(size_t)B_ROWS * S_DIM];
__device__ __align__(16) int8_t g_kb [(size_t)B_ROWS * S_DIM];
__device__ __align__(16) int8_t g_ha [(size_t)B_ROWS * S_DIM];
__device__ __align__(16) int8_t g_hb [(size_t)B_ROWS * S_DIM];
__device__ float g_xs [B_ROWS];
__device__ float g_svs[S_DIM];
__device__ float g_w1s[S_DIM];
__device__ float g_w2s[S_DIM];
__device__ float g_xn [B_ROWS];
__device__ float g_svn[S_DIM];
__device__ float g_part[32 * B_ROWS * 2];

// ============================================================================
// PTX helpers
// ============================================================================
__device__ __forceinline__ uint32_t smem_u32(const void* p) {
    uint32_t a;
    asm("{ .reg .u64 t; cvta.to.shared.u64 t, %1; cvt.u32.u64 %0, t; }"
        : "=r"(a) : "l"(p));
    return a;
}

__device__ __forceinline__ void cp16(uint32_t s, const void* g) {
    asm volatile("cp.async.cg.shared.global [%0], [%1], 16;"
                 :: "r"(s), "l"((unsigned long long)(uintptr_t)g) : "memory");
}
#define CP_COMMIT()  asm volatile("cp.async.commit_group;" ::: "memory")
#define CP_WAIT0()   asm volatile("cp.async.wait_group 0;" ::: "memory")

__device__ __forceinline__ void ldm_x4(uint32_t* r, uint32_t saddr) {
    asm volatile("ldmatrix.sync.aligned.m8n8.x4.shared.b16 {%0,%1,%2,%3}, [%4];"
                 : "=r"(r[0]), "=r"(r[1]), "=r"(r[2]), "=r"(r[3]) : "r"(saddr));
}

#define IMMA(C, A, B0, B1)                                                     \
    asm volatile(                                                              \
        "mma.sync.aligned.m16n8k32.row.col.s32.s8.s8.s32 "                     \
        "{%0,%1,%2,%3}, {%4,%5,%6,%7}, {%8,%9}, {%0,%1,%2,%3};"                \
        : "+r"((C)[0]), "+r"((C)[1]), "+r"((C)[2]), "+r"((C)[3])               \
        : "r"((A)[0]), "r"((A)[1]), "r"((A)[2]), "r"((A)[3]),                  \
          "r"(B0), "r"(B1))

// fp32 -> 2-slice int8 (inv = 127/scale), clamped
__device__ __forceinline__ void qpair(float v, float inv, int8_t& o1, int8_t& o2) {
    float q = fminf(fmaxf(v * inv, -127.0f), 127.0f);
    float R = rintf(q);
    o1 = (int8_t)(int)R;
    o2 = (int8_t)(int)rintf((q - R) * 254.0f);
}

// ============================================================================
// Row-wise 2-slice quantizer (warp per row)
// ============================================================================
template <int COLS, bool NORM>
__global__ void quant_rows(const float* __restrict__ src,
                           int8_t* __restrict__ q1, int8_t* __restrict__ q2,
                           float* __restrict__ sOut, float* __restrict__ nrm) {
    int row  = blockIdx.x * 8 + (threadIdx.x >> 5);
    int lane = threadIdx.x & 31;
    const float4* s4 = (const float4*)(src + (size_t)row * COLS);
    float4 vb[COLS / 128];
    float mx = 0.f, ss = 0.f;
    #pragma unroll
    for (int i = 0; i < COLS / 128; ++i) {
        float4 v = s4[i * 32 + lane];
        vb[i] = v;
        mx = fmaxf(mx, fmaxf(fmaxf(fabsf(v.x), fabsf(v.y)),
                             fmaxf(fabsf(v.z), fabsf(v.w))));
        if (NORM)
            ss = fmaf(v.x, v.x, fmaf(v.y, v.y, fmaf(v.z, v.z, fmaf(v.w, v.w, ss))));
    }
    #pragma unroll
    for (int o = 16; o; o >>= 1) {
        mx = fmaxf(mx, __shfl_xor_sync(0xffffffffu, mx, o));
        if (NORM) ss += __shfl_xor_sync(0xffffffffu, ss, o);
    }
    float s = mx > 0.f ? mx : 1.0f;
    if (lane == 0) {
        sOut[row] = s;
        if (NORM) nrm[row] = ss;
    }
    float inv = 127.0f / s;
    #pragma unroll
    for (int i = 0; i < COLS / 128; ++i) {
        char4 c1, c2;
        qpair(vb[i].x, inv, (int8_t&)c1.x, (int8_t&)c2.x);
        qpair(vb[i].y, inv, (int8_t&)c1.y, (int8_t&)c2.y);
        qpair(vb[i].z, inv, (int8_t&)c1.z, (int8_t&)c2.z);
        qpair(vb[i].w, inv, (int8_t&)c1.w, (int8_t&)c2.w);
        size_t o = (size_t)row * COLS + i * 128 + lane * 4;
        *(char4*)(q1 + o) = c1;
        *(char4*)(q2 + o) = c2;
    }
}

// ============================================================================
// GEMM1 persistent: k = exp(g*(2*dot - xn - svn)) -> g_ka/g_kb
// grid (8, 37): CTA keeps its sv col-tile (B1+B2) resident in SMEM and
// streams row-tiles of x through a 2-stage A buffer (chunk = K-half of 128).
// ============================================================================
constexpr int G1_YSTRIDE = 37;   // 8*37 = 296 CTAs = 2/SM exactly

__global__ void __launch_bounds__(NTH, 2)
gemm1_persist(const int8_t* __restrict__ A1p, const int8_t* __restrict__ A2p,
              const int8_t* __restrict__ B1p, const int8_t* __restrict__ B2p,
              const float* __restrict__ sA, const float* __restrict__ sB) {
    constexpr int ROWB    = 144;
    constexpr int B_HALF  = 2 * 128 * ROWB;   // 36864 (B1+B2 of one K-half)
    constexpr int B_SLICE = 128 * ROWB;       // 18432
    constexpr int A_BASE  = 2 * B_HALF;       // 73728
    constexpr int A_STAGE = 2 * 64 * ROWB;    // 18432 (A1+A2 of one chunk)
    constexpr int A_SLICE = 64 * ROWB;        // 9216
    constexpr int NRT     = B_ROWS / BM;      // 1024 row tiles total

    extern __shared__ char smem[];
    const uint32_t sb0 = smem_u32(smem);
    const int tid = threadIdx.x, wid = tid >> 5, lane = tid & 31;
    const int g = lane >> 2, tg = lane & 3;
    const int warp_m = wid & 1, warp_n = wid >> 1;
    const int colBase = blockIdx.x * BN;

    const int a_row = warp_m * 32 + (lane & 7) + ((lane >> 3) & 1) * 8;
    const int a_kby = (lane >> 4) * 16;
    const int b_row = warp_n * 32 + (lane & 7) + (lane >> 4) * 8;
    const int b_kby = ((lane >> 3) & 1) * 16;

    // ---- resident B: both K-halves, both slices (73.7 KB) ----
    #pragma unroll
    for (int u = tid; u < 128 * 8; u += NTH) {
        int row = u >> 3, seg = u & 7;
        #pragma unroll
        for (int half = 0; half < 2; ++half) {
            size_t go = (size_t)(colBase + row) * FEAT + half * 128 + seg * 16;
            uint32_t d = sb0 + half * B_HALF + row * ROWB + seg * 16;
            cp16(d, B1p + go);
            cp16(d + B_SLICE, B2p + go);
        }
    }

    auto load_A = [&](int rtg, int half, int stage) {
        const int rowBase = rtg * BM;
        #pragma unroll
        for (int u = tid; u < 64 * 8; u += NTH) {
            int row = u >> 3, seg = u & 7;
            size_t go = (size_t)(rowBase + row) * FEAT + half * 128 + seg * 16;
            uint32_t d = sb0 + A_BASE + stage * A_STAGE + row * ROWB + seg * 16;
            cp16(d, A1p + go);
            cp16(d + A_SLICE, A2p + go);
        }
        CP_COMMIT();   // (first call also commits the B loads above)
    };

    load_A(blockIdx.y, 0, 0);

    int C1[2][4][4], Cx[2][4][4];
    int t = 0;
    for (int rtg = blockIdx.y; rtg < NRT; rtg += G1_YSTRIDE) {
        #pragma unroll
        for (int half = 0; half < 2; ++half, ++t) {
            CP_WAIT0();
            __syncthreads();
            // prefetch next chunk (overlaps compute + epilogue)
            if (half == 0) {
                load_A(rtg, 1, (t + 1) & 1);
            } else if (rtg + G1_YSTRIDE < NRT) {
                load_A(rtg + G1_YSTRIDE, 0, (t + 1) & 1);
            }

            if (half == 0) {
                #pragma unroll
                for (int mt = 0; mt < 2; ++mt)
                    #pragma unroll
                    for (int nt = 0; nt < 4; ++nt)
                        #pragma unroll
                        for (int i = 0; i < 4; ++i) { C1[mt][nt][i] = 0; Cx[mt][nt][i] = 0; }
            }

            const uint32_t aBase = sb0 + A_BASE + (t & 1) * A_STAGE;
            const uint32_t bBase = sb0 + half * B_HALF;

            #pragma unroll
            for (int kk = 0; kk < 4; ++kk) {
                const uint32_t ab = aBase + (uint32_t)(a_row * ROWB + kk * 32 + a_kby);
                const uint32_t bb = bBase + (uint32_t)(b_row * ROWB + kk * 32 + b_kby);
                uint32_t aF[2][4], bF[2][4], bG[2][4];
                #pragma unroll
                for (int mt = 0; mt < 2; ++mt) ldm_x4(aF[mt], ab + mt * 16 * ROWB);
                #pragma unroll
                for (int ne = 0; ne < 2; ++ne) ldm_x4(bF[ne], bb + ne * 16 * ROWB);
                #pragma unroll
                for (int ne = 0; ne < 2; ++ne) ldm_x4(bG[ne], bb + B_SLICE + ne * 16 * ROWB);
                #pragma unroll
                for (int mt = 0; mt < 2; ++mt)
                    #pragma unroll
                    for (int nt = 0; nt < 4; ++nt) {
                        const int ne = nt >> 1, h2 = (nt & 1) * 2;
                        IMMA(C1[mt][nt], aF[mt], bF[ne][h2], bF[ne][h2 + 1]);
                    }
                #pragma unroll
                for (int mt = 0; mt < 2; ++mt)
                    #pragma unroll
                    for (int nt = 0; nt < 4; ++nt) {
                        const int ne = nt >> 1, h2 = (nt & 1) * 2;
                        IMMA(Cx[mt][nt], aF[mt], bG[ne][h2], bG[ne][h2 + 1]);
                    }
                #pragma unroll
                for (int mt = 0; mt < 2; ++mt) ldm_x4(aF[mt], ab + A_SLICE + mt * 16 * ROWB);
                #pragma unroll
                for (int mt = 0; mt < 2; ++mt)
                    #pragma unroll
                    for (int nt = 0; nt < 4; ++nt) {
                        const int ne = nt >> 1, h2 = (nt & 1) * 2;
                        IMMA(Cx[mt][nt], aF[mt], bF[ne][h2], bF[ne][h2 + 1]);
                    }
            }

            if (half == 1) {
                // epilogue for row-tile rtg
                const int rowBase = rtg * BM;
                #pragma unroll
                for (int mt = 0; mt < 2; ++mt) {
                    const int r0 = rowBase + warp_m * 32 + mt * 16 + g;
                    const float sa0 = sA[r0], sa1 = sA[r0 + 8];
                    const float xn0 = g_xn[r0], xn1 = g_xn[r0 + 8];
                    #pragma unroll
                    for (int nt = 0; nt < 4; ++nt) {
                        const int cidx = colBase + warp_n * 32 + nt * 8 + 2 * tg;
                        const float q0 = sB[cidx] * INVQ, q1 = sB[cidx + 1] * INVQ;
                        float d00 = ((float)C1[mt][nt][0] + (float)Cx[mt][nt][0] * INV254) * (sa0 * q0);
                        float d01 = ((float)C1[mt][nt][1] + (float)Cx[mt][nt][1] * INV254) * (sa0 * q1);
                        float d10 = ((float)C1[mt][nt][2] + (float)Cx[mt][nt][2] * INV254) * (sa1 * q0);
                        float d11 = ((float)C1[mt][nt][3] + (float)Cx[mt][nt][3] * INV254) * (sa1 * q1);
                        float sn0 = g_svn[cidx], sn1 = g_svn[cidx + 1];
                        float k00 = __expf(GAMMA_F * (2.f * d00 - xn0 - sn0));
                        float k01 = __expf(GAMMA_F * (2.f * d01 - xn0 - sn1));
                        float k10 = __expf(GAMMA_F * (2.f * d10 - xn1 - sn0));
                        float k11 = __expf(GAMMA_F * (2.f * d11 - xn1 - sn1));
                        char2 p1, p2;
                        size_t o0 = (size_t)r0 * S_DIM + cidx;
                        size_t o1 = (size_t)(r0 + 8) * S_DIM + cidx;
                        qpair(k00, 127.0f, (int8_t&)p1.x, (int8_t&)p2.x);
                        qpair(k01, 127.0f, (int8_t&)p1.y, (int8_t&)p2.y);
                        *(char2*)(g_ka + o0) = p1; *(char2*)(g_kb + o0) = p2;
                        qpair(k10, 127.0f, (int8_t&)p1.x, (int8_t&)p2.x);
                        qpair(k11, 127.0f, (int8_t&)p1.y, (int8_t&)p2.y);
                        *(char2*)(g_ka + o1) = p1; *(char2*)(g_kb + o1) = p2;
                    }
                }
            }
        }
    }
}

// ============================================================================
// Int8 2-slice GEMM (G2/G3).  D[m,n] = sum_k A[m,k] * B[n,k]
//  EPI 1: h = relu(dot + b1) -> g_ha/g_hb (fixed scale H_SCALE)
//  EPI 2: v = relu(dot + b2); head partials -> g_part
// ============================================================================
template <int KTOT, int BKT, int EPI>
__global__ void __launch_bounds__(NTH, 2)
gemm_i8(const int8_t* __restrict__ A1p, const int8_t* __restrict__ A2p,
        const int8_t* __restrict__ B1p, const int8_t* __restrict__ B2p,
        const float* __restrict__ sA, float sAc, const float* __restrict__ sB,
        const float* __restrict__ bias, const float* __restrict__ Wh) {
    constexpr int ROWB    = BKT + 16;
    constexpr int A_PLANE = BM * ROWB;
    constexpr int B_PLANE = BN * ROWB;
    constexpr int OFF_A1  = 0;
    constexpr int OFF_A2  = A_PLANE;
    constexpr int OFF_B1  = 2 * A_PLANE;
    constexpr int OFF_B2  = 2 * A_PLANE + B_PLANE;
    constexpr int STAGE   = 2 * A_PLANE + 2 * B_PLANE;
    constexpr int NKK     = BKT / 32;
    constexpr int NCHUNK  = KTOT / BKT;

    extern __shared__ char smem[];
    const uint32_t sb0 = smem_u32(smem);

    const int tid    = threadIdx.x;
    const int wid    = tid >> 5;
    const int lane   = tid & 31;
    const int g      = lane >> 2;
    const int tg     = lane & 3;
    const int warp_m = wid & 1;
    const int warp_n = wid >> 1;

    const int rowBase = blockIdx.y * BM;
    const int colBase = blockIdx.x * BN;

    const int a_row = warp_m * 32 + (lane & 7) + ((lane >> 3) & 1) * 8;
    const int a_kby = (lane >> 4) * 16;
    const int b_row = warp_n * 32 + (lane & 7) + (lane >> 4) * 8;
    const int b_kby = ((lane >> 3) & 1) * 16;

    auto load_stage = [&](int c) {
        uint32_t s0 = sb0 + (c & 1) * STAGE;
        const int kc = c * BKT;
        constexpr int SEG = BKT / 16;
        #pragma unroll
        for (int u = tid; u < BM * SEG; u += NTH) {
            int row = u / SEG, seg = u % SEG;
            size_t go = (size_t)(rowBase + row) * KTOT + kc + seg * 16;
            cp16(s0 + OFF_A1 + row * ROWB + seg * 16, A1p + go);
            cp16(s0 + OFF_A2 + row * ROWB + seg * 16, A2p + go);
        }
        #pragma unroll
        for (int u = tid; u < BN * SEG; u += NTH) {
            int row = u / SEG, seg = u % SEG;
            size_t go = (size_t)(colBase + row) * KTOT + kc + seg * 16;
            cp16(s0 + OFF_B1 + row * ROWB + seg * 16, B1p + go);
            cp16(s0 + OFF_B2 + row * ROWB + seg * 16, B2p + go);
        }
        CP_COMMIT();
    };

    int C1[2][4][4], Cx[2][4][4];
    #pragma unroll
    for (int mt = 0; mt < 2; ++mt)
        #pragma unroll
        for (int nt = 0; nt < 4; ++nt)
            #pragma unroll
            for (int i = 0; i < 4; ++i) { C1[mt][nt][i] = 0; Cx[mt][nt][i] = 0; }

    load_stage(0);

    for (int c = 0; c < NCHUNK; ++c) {
        CP_WAIT0();
        __syncthreads();
        if (c + 1 < NCHUNK) load_stage(c + 1);

        const uint32_t sb = sb0 + (c & 1) * STAGE;

        #pragma unroll
        for (int kk = 0; kk < NKK; ++kk) {
            const uint32_t ab = sb + (uint32_t)(a_row * ROWB + kk * 32 + a_kby);
            const uint32_t bb = sb + (uint32_t)(b_row * ROWB + kk * 32 + b_kby);

            uint32_t aF[2][4], bF[2][4], bG[2][4];

            #pragma unroll
            for (int mt = 0; mt < 2; ++mt) ldm_x4(aF[mt], ab + OFF_A1 + mt * 16 * ROWB);
            #pragma unroll
            for (int ne = 0; ne < 2; ++ne) ldm_x4(bF[ne], bb + OFF_B1 + ne * 16 * ROWB);
            #pragma unroll
            for (int ne = 0; ne < 2; ++ne) ldm_x4(bG[ne], bb + OFF_B2 + ne * 16 * ROWB);

            #pragma unroll
            for (int mt = 0; mt < 2; ++mt)
                #pragma unroll
                for (int nt = 0; nt < 4; ++nt) {
                    const int ne = nt >> 1, h2 = (nt & 1) * 2;
                    IMMA(C1[mt][nt], aF[mt], bF[ne][h2], bF[ne][h2 + 1]);
                }
            #pragma unroll
            for (int mt = 0; mt < 2; ++mt)
                #pragma unroll
                for (int nt = 0; nt < 4; ++nt) {
                    const int ne = nt >> 1, h2 = (nt & 1) * 2;
                    IMMA(Cx[mt][nt], aF[mt], bG[ne][h2], bG[ne][h2 + 1]);
                }
            #pragma unroll
            for (int mt = 0; mt < 2; ++mt) ldm_x4(aF[mt], ab + OFF_A2 + mt * 16 * ROWB);
            #pragma unroll
            for (int mt = 0; mt < 2; ++mt)
                #pragma unroll
                for (int nt = 0; nt < 4; ++nt) {
                    const int ne = nt >> 1, h2 = (nt & 1) * 2;
                    IMMA(Cx[mt][nt], aF[mt], bF[ne][h2], bF[ne][h2 + 1]);
                }
        }
    }

    // ---------------- Epilogue ----------------
    float o0s[2][2], o1s[2][2];
    if constexpr (EPI == 2) {
        #pragma unroll
        for (int mt = 0; mt < 2; ++mt) { o0s[mt][0] = o0s[mt][1] = 0.f;
                                         o1s[mt][0] = o1s[mt][1] = 0.f; }
    }

    #pragma unroll
    for (int mt = 0; mt < 2; ++mt) {
        const int r0 = rowBase + warp_m * 32 + mt * 16 + g;
        const float sa0 = sA ? sA[r0] : sAc;
        const float sa1 = sA ? sA[r0 + 8] : sAc;

        #pragma unroll
        for (int nt = 0; nt < 4; ++nt) {
            const int cidx = colBase + warp_n * 32 + nt * 8 + 2 * tg;
            const float q0 = sB[cidx] * INVQ, q1 = sB[cidx + 1] * INVQ;
            float d00 = ((float)C1[mt][nt][0] + (float)Cx[mt][nt][0] * INV254) * (sa0 * q0);
            float d01 = ((float)C1[mt][nt][1] + (float)Cx[mt][nt][1] * INV254) * (sa0 * q1);
            float d10 = ((float)C1[mt][nt][2] + (float)Cx[mt][nt][2] * INV254) * (sa1 * q0);
            float d11 = ((float)C1[mt][nt][3] + (float)Cx[mt][nt][3] * INV254) * (sa1 * q1);

            if constexpr (EPI == 1) {
                const float invh = 127.0f / H_SCALE;
                float b0v = bias[cidx], b1v = bias[cidx + 1];
                float h00 = fmaxf(d00 + b0v, 0.f), h01 = fmaxf(d01 + b1v, 0.f);
                float h10 = fmaxf(d10 + b0v, 0.f), h11 = fmaxf(d11 + b1v, 0.f);
                char2 p1, p2;
                size_t o0 = (size_t)r0 * S_DIM + cidx;
                size_t o1 = (size_t)(r0 + 8) * S_DIM + cidx;
                qpair(h00, invh, (int8_t&)p1.x, (int8_t&)p2.x);
                qpair(h01, invh, (int8_t&)p1.y, (int8_t&)p2.y);
                *(char2*)(g_ha + o0) = p1; *(char2*)(g_hb + o0) = p2;
                qpair(h10, invh, (int8_t&)p1.x, (int8_t&)p2.x);
                qpair(h11, invh, (int8_t&)p1.y, (int8_t&)p2.y);
                *(char2*)(g_ha + o1) = p1; *(char2*)(g_hb + o1) = p2;
            } else {
                float b0v = bias[cidx], b1v = bias[cidx + 1];
                float w00 = Wh[cidx],         w01 = Wh[cidx + 1];
                float w10 = Wh[S_DIM + cidx], w11 = Wh[S_DIM + cidx + 1];
                float v00 = fmaxf(d00 + b0v, 0.f), v01 = fmaxf(d01 + b1v, 0.f);
                float v10 = fmaxf(d10 + b0v, 0.f), v11 = fmaxf(d11 + b1v, 0.f);
                o0s[mt][0] = fmaf(v00, w00, fmaf(v01, w01, o0s[mt][0]));
                o1s[mt][0] = fmaf(v00, w10, fmaf(v01, w11, o1s[mt][0]));
                o0s[mt][1] = fmaf(v10, w00, fmaf(v11, w01, o0s[mt][1]));
                o1s[mt][1] = fmaf(v10, w10, fmaf(v11, w11, o1s[mt][1]));
            }
        }
    }

    if constexpr (EPI == 2) {
        #pragma unroll
        for (int mt = 0; mt < 2; ++mt)
            #pragma unroll
            for (int rh = 0; rh < 2; ++rh) {
                float a = o0s[mt][rh], b = o1s[mt][rh];
                a += __shfl_xor_sync(0xffffffffu, a, 1);
                a += __shfl_xor_sync(0xffffffffu, a, 2);
                b += __shfl_xor_sync(0xffffffffu, b, 1);
                b += __shfl_xor_sync(0xffffffffu, b, 2);
                o0s[mt][rh] = a; o1s[mt][rh] = b;
            }
        if (tg == 0) {
            int slot = blockIdx.x * 4 + warp_n;
            #pragma unroll
            for (int mt = 0; mt < 2; ++mt)
                #pragma unroll
                for (int rh = 0; rh < 2; ++rh) {
                    int row = rowBase + warp_m * 32 + mt * 16 + g + rh * 8;
                    size_t base = ((size_t)slot * B_ROWS + row) * 2;
                    g_part[base]     = o0s[mt][rh];
                    g_part[base + 1] = o1s[mt][rh];
                }
        }
    }
}

// ============================================================================
// Head reduction
// ============================================================================
__global__ void head_final(const float* __restrict__ bh, float* __restrict__ out) {
    int i = blockIdx.x * blockDim.x + threadIdx.x;
    if (i < B_ROWS * 2) {
        float s = bh[i & 1];
        #pragma unroll
        for (int t = 0; t < 32; ++t) s += g_part[(size_t)t * B_ROWS * 2 + i];
        out[i] = s;
    }
}

// ============================================================================
// Launcher — GEMM1/GEMM2 at launch indices 3/4 (ncu capture window)
// ============================================================================
extern "C" void kernel_launch(void* const* d_in, const int* in_sizes, int n_in,
                              void* d_out, int out_size) {
    (void)in_sizes; (void)n_in; (void)out_size;
    const float* x  = (const float*)d_in[0];
    const float* sv = (const float*)d_in[1];
    const float* W1 = (const float*)d_in[2];
    const float* b1 = (const float*)d_in[3];
    const float* W2 = (const float*)d_in[4];
    const float* b2 = (const float*)d_in[5];
    const float* Wh = (const float*)d_in[6];
    const float* bh = (const float*)d_in[7];
    float* out = (float*)d_out;

    static int8_t *xa, *xb, *sva, *svb, *w1a, *w1b, *w2a, *w2b, *ka, *kb, *ha, *hb;
    static float *xs, *svs, *w1s, *w2s, *xn, *svn;
    static bool got = false;
    if (!got) {
        cudaGetSymbolAddress((void**)&xa,  g_xa);  cudaGetSymbolAddress((void**)&xb,  g_xb);
        cudaGetSymbolAddress((void**)&sva, g_sva); cudaGetSymbolAddress((void**)&svb, g_svb);
        cudaGetSymbolAddress((void**)&w1a, g_w1a); cudaGetSymbolAddress((void**)&w1b, g_w1b);
        cudaGetSymbolAddress((void**)&w2a, g_w2a); cudaGetSymbolAddress((void**)&w2b, g_w2b);
        cudaGetSymbolAddress((void**)&ka,  g_ka);  cudaGetSymbolAddress((void**)&kb,  g_kb);
        cudaGetSymbolAddress((void**)&ha,  g_ha);  cudaGetSymbolAddress((void**)&hb,  g_hb);
        cudaGetSymbolAddress((void**)&xs,  g_xs);  cudaGetSymbolAddress((void**)&svs, g_svs);
        cudaGetSymbolAddress((void**)&w1s, g_w1s); cudaGetSymbolAddress((void**)&w2s, g_w2s);
        cudaGetSymbolAddress((void**)&xn,  g_xn);  cudaGetSymbolAddress((void**)&svn, g_svn);
        cudaFuncSetAttribute((const void*)gemm1_persist,
                             cudaFuncAttributeMaxDynamicSharedMemorySize, SMEM_G1);
        cudaFuncSetAttribute((const void*)gemm_i8<S_DIM, 128, 1>,
                             cudaFuncAttributeMaxDynamicSharedMemorySize, SMEM_G2);
        cudaFuncSetAttribute((const void*)gemm_i8<S_DIM, 128, 2>,
                             cudaFuncAttributeMaxDynamicSharedMemorySize, SMEM_G2);
        got = true;
    }

    dim3 grid2(S_DIM / BN, B_ROWS / BM);   // (8, 1024)

    // idx 0-2: quantize x (+norm), sv (+norm), W1
    quant_rows<FEAT, true ><<<B_ROWS / 8, 256>>>(x,  xa,  xb,  xs,  xn);
    quant_rows<FEAT, true ><<<S_DIM  / 8, 256>>>(sv, sva, svb, svs, svn);
    quant_rows<S_DIM, false><<<S_DIM / 8, 256>>>(W1, w1a, w1b, w1s, nullptr);
    // idx 3: GEMM1 persistent (resident sv tile, streamed x)
    gemm1_persist<<<dim3(S_DIM / BN, G1_YSTRIDE), NTH, SMEM_G1>>>(
        xa, xb, sva, svb, xs, svs);
    // idx 4: GEMM2 (hidden1 -> int8 h, fixed scale H_SCALE; fused quant)
    gemm_i8<S_DIM, 128, 1><<<grid2, NTH, SMEM_G2>>>(ka, kb, w1a, w1b, nullptr, 1.0f, w1s,
                                                    b1, nullptr);
    // idx 5: quantize W2
    quant_rows<S_DIM, false><<<S_DIM / 8, 256>>>(W2, w2a, w2b, w2s, nullptr);
    // idx 6: GEMM3 (hidden2 + head partials; A-scale = H_SCALE constant)
    gemm_i8<S_DIM, 128, 2><<<grid2, NTH, SMEM_G2>>>(ha, hb, w2a, w2b, nullptr, H_SCALE, w2s,
                                                    b2, Wh);
    // idx 7: head reduction
    head_final<<<(B_ROWS * 2 + 255) / 256, 256>>>(bh, out);
}